// round 17
// baseline (speedup 1.0000x reference)
#include <cuda_runtime.h>
#include <cuda_fp16.h>
#include <stdint.h>

#define N_NODES     50000
#define N_EDGES     500000
#define D_FEAT      128
#define OUT_CLASSES 64
#define PDIM        128   // [0:64) = Pu (+bias folded), [64:128) = Pv

// Per-node projections in fp16; 12.8 MB, L2-resident.
__device__ __align__(16) __half g_P[N_NODES * PDIM];

// ---------------------------------------------------------------------------
// Single-pass fp16 mma (legacy mma.sync — tcgen05 unavailable at compute_103).
// ---------------------------------------------------------------------------
__device__ __forceinline__ void mma_f16(float d[4], const uint32_t a[4], const uint32_t b[2]) {
    asm volatile(
        "mma.sync.aligned.m16n8k16.row.col.f32.f16.f16.f32 "
        "{%0,%1,%2,%3}, {%4,%5,%6,%7}, {%8,%9}, {%0,%1,%2,%3};\n"
        : "+f"(d[0]), "+f"(d[1]), "+f"(d[2]), "+f"(d[3])
        : "r"(a[0]), "r"(a[1]), "r"(a[2]), "r"(a[3]), "r"(b[0]), "r"(b[1]));
}

// ---------------------------------------------------------------------------
// Kernel 1: node projection GEMM (measured ~12.4us, unchanged from r15/16).
//   P[n][j] = sum_k h[n][k] * Wn[j][k] (+ b[j] for j<64)
// Tile 128m x 128n x 128k, 512 threads, 4x4 grid of 32x32 warp tiles.
// smem: A 128x68 + B 128x68 u32 pairs = 69.6KB -> 2 CTAs/SM.
// ---------------------------------------------------------------------------
#define GM   128
#define GTHREADS 512
#define ST   68   // uint32 per row (64 f16x2 pairs + 4 pad); 68 mod 32 = 4
#define GEMM_SMEM ((128 + 128) * ST * 4)   // 69,632 B

__global__ __launch_bounds__(GTHREADS, 2)
void node_gemm_f16(const float* __restrict__ h,
                   const float* __restrict__ W,
                   const float* __restrict__ b) {
    extern __shared__ uint32_t sh[];
    uint32_t* Ah = sh;                // [128][ST] f16x2 pairs, k-major
    uint32_t* Bs = sh + 128 * ST;     // [128][ST] f16x2 pairs, k-major

    const int tid = threadIdx.x;
    const int n0  = blockIdx.x * GM;

    // Stage A (h tile, 128 x 128 f32 -> f16x2), coalesced float4
    #pragma unroll
    for (int it = 0; it < 8; ++it) {
        int idx = tid + it * GTHREADS;     // 0..4095
        int r  = idx >> 5;                 // 0..127
        int c4 = idx & 31;                 // float4 index; k = c4*4
        int node = n0 + r;
        float4 v = make_float4(0.f, 0.f, 0.f, 0.f);
        if (node < N_NODES)
            v = __ldg((const float4*)&h[(size_t)node * D_FEAT + c4 * 4]);
        __half2 h0 = __floats2half2_rn(v.x, v.y);
        __half2 h1 = __floats2half2_rn(v.z, v.w);
        *(uint2*)&Ah[r * ST + c4 * 2] = make_uint2(*(uint32_t*)&h0, *(uint32_t*)&h1);
    }
    // Stage B (Wn, 128 x 128 f32 -> f16x2), coalesced float4 per row
    #pragma unroll
    for (int it = 0; it < 8; ++it) {
        int idx = tid + it * GTHREADS;     // 0..4095
        int j  = idx >> 5;                 // 0..127
        int c4 = idx & 31;
        const float* ws = (j < OUT_CLASSES)
            ? &W[(size_t)j * 256 + c4 * 4]
            : &W[(size_t)(j - OUT_CLASSES) * 256 + 128 + c4 * 4];
        float4 v = __ldg((const float4*)ws);
        __half2 h0 = __floats2half2_rn(v.x, v.y);
        __half2 h1 = __floats2half2_rn(v.z, v.w);
        *(uint2*)&Bs[j * ST + c4 * 2] = make_uint2(*(uint32_t*)&h0, *(uint32_t*)&h1);
    }
    __syncthreads();

    const int wid    = tid >> 5;
    const int lane   = tid & 31;
    const int warp_m = wid & 3;        // 4 warps over 128 m
    const int warp_n = wid >> 2;       // 4 warps over 128 n
    const int m_base = warp_m * 32;
    const int n_base = warp_n * 32;
    const int lr = lane >> 2;          // 0..7
    const int lc = lane & 3;           // 0..3

    float acc[2][4][4];
    #pragma unroll
    for (int a = 0; a < 2; ++a)
        #pragma unroll
        for (int bn = 0; bn < 4; ++bn)
            #pragma unroll
            for (int c = 0; c < 4; ++c) acc[a][bn][c] = 0.0f;

    #pragma unroll 2
    for (int kc = 0; kc < 8; ++kc) {
        const int p0 = kc * 8 + lc;

        uint32_t bb[4][2];
        #pragma unroll
        for (int bn = 0; bn < 4; ++bn) {
            int nb = (n_base + bn * 8 + lr) * ST + p0;
            bb[bn][0] = Bs[nb];
            bb[bn][1] = Bs[nb + 4];
        }
        uint32_t ah[2][4];
        #pragma unroll
        for (int am = 0; am < 2; ++am) {
            int base = (m_base + am * 16 + lr) * ST + p0;
            ah[am][0] = Ah[base];
            ah[am][1] = Ah[base + 8 * ST];
            ah[am][2] = Ah[base + 4];
            ah[am][3] = Ah[base + 8 * ST + 4];
        }
        #pragma unroll
        for (int am = 0; am < 2; ++am)
            #pragma unroll
            for (int bn = 0; bn < 4; ++bn)
                mma_f16(acc[am][bn], ah[am], bb[bn]);
    }

    // Epilogue: fp16 P, bias folded into Pu columns (warp_n<2 <=> j<64).
    #pragma unroll
    for (int am = 0; am < 2; ++am) {
        int row = m_base + am * 16 + lr;
        #pragma unroll
        for (int bn = 0; bn < 4; ++bn) {
            int j = n_base + bn * 8 + 2 * lc;
            float bx = 0.f, by = 0.f;
            if (warp_n < 2) {
                float2 bv = __ldg((const float2*)&b[j]);
                bx = bv.x; by = bv.y;
            }
            int node = n0 + row;
            if (node < N_NODES) {
                __half2 v0 = __floats2half2_rn(acc[am][bn][0] + bx,
                                               acc[am][bn][1] + by);
                *(__half2*)&g_P[(size_t)node * PDIM + j] = v0;
            }
            int node2 = n0 + row + 8;
            if (node2 < N_NODES) {
                __half2 v1 = __floats2half2_rn(acc[am][bn][2] + bx,
                                               acc[am][bn][3] + by);
                *(__half2*)&g_P[(size_t)node2 * PDIM + j] = v1;
            }
        }
    }
}

// ---------------------------------------------------------------------------
// Kernel 2: edge scatter, lean issue stream.
//  - half-warp owns 4 consecutive edges; indices fetched as ONE int4 per
//    array (or 2x ulonglong2 for int64) instead of 8 scalar LDGs
//  - 500000 % 8 == 0: each warp is fully valid or fully out of range ->
//    single warp-uniform early-out, unguarded vector stores
//  - Pu+Pv added in half2 (HADD2), single cvt to fp32 (adds a 4th ~2e-4
//    rounding term; total ~4.2e-4 < 1e-3)
//  - all offsets 32-bit unsigned
// Gather pattern unchanged: 8 outstanding uint2 gathers per thread (MLP 8).
// ---------------------------------------------------------------------------
__global__ __launch_bounds__(256)
void edge_scatter_kernel(const void* __restrict__ srcp,
                         const void* __restrict__ dstp,
                         float* __restrict__ out) {
    __shared__ int s_is64;
    if (threadIdx.x == 0) {
        const long long* p64 = (const long long*)srcp;
        int ok = 1;
        #pragma unroll
        for (int i = 0; i < 8; ++i) {
            long long v = p64[i];
            if (v < 0 || v >= (long long)N_NODES) ok = 0;
        }
        s_is64 = ok;
    }
    __syncthreads();
    const int is64 = s_is64;

    const int warp = threadIdx.x >> 5;
    const int lane = threadIdx.x & 31;
    const int half = lane >> 4;
    const int sub  = lane & 15;
    const unsigned ebase = (blockIdx.x * 8u + warp) * 8u + half * 4u;  // 4 edges
    if (ebase >= N_EDGES) return;   // warp-uniform (N_EDGES % 8 == 0)

    // Vector index loads: 4 consecutive edges per half-warp.
    unsigned s[4], d[4];
    if (is64) {
        const ulonglong2* sp = (const ulonglong2*)((const long long*)srcp + ebase);
        const ulonglong2* dp = (const ulonglong2*)((const long long*)dstp + ebase);
        ulonglong2 s01 = __ldg(sp), s23 = __ldg(sp + 1);
        ulonglong2 d01 = __ldg(dp), d23 = __ldg(dp + 1);
        s[0] = (unsigned)s01.x; s[1] = (unsigned)s01.y;
        s[2] = (unsigned)s23.x; s[3] = (unsigned)s23.y;
        d[0] = (unsigned)d01.x; d[1] = (unsigned)d01.y;
        d[2] = (unsigned)d23.x; d[3] = (unsigned)d23.y;
    } else {
        int4 si = __ldg((const int4*)((const int*)srcp + ebase));
        int4 di = __ldg((const int4*)((const int*)dstp + ebase));
        s[0] = si.x; s[1] = si.y; s[2] = si.z; s[3] = si.w;
        d[0] = di.x; d[1] = di.y; d[2] = di.z; d[3] = di.w;
    }

    // Front-batch all 8 gathers (uint2 = 4 halves; 16 lanes x 8B = 128B/row).
    const unsigned cb = sub * 4u;
    uint2 gu[4], gv[4];
    #pragma unroll
    for (int i = 0; i < 4; ++i) {
        gu[i] = *(const uint2*)&g_P[s[i] * (unsigned)PDIM + cb];
        gv[i] = *(const uint2*)&g_P[d[i] * (unsigned)PDIM + (unsigned)OUT_CLASSES + cb];
    }

    #pragma unroll
    for (int i = 0; i < 4; ++i) {
        __half2 x0 = __hadd2(*(__half2*)&gu[i].x, *(__half2*)&gv[i].x);
        __half2 x1 = __hadd2(*(__half2*)&gu[i].y, *(__half2*)&gv[i].y);
        float2 f0 = __half22float2(x0);
        float2 f1 = __half22float2(x1);
        float4 r = make_float4(f0.x, f0.y, f1.x, f1.y);
        __stcs((float4*)&out[(size_t)(ebase + i) * OUT_CLASSES + cb], r);
    }
}

// ---------------------------------------------------------------------------
// Launch. Inputs: h[50000*128] f32, src[500000], dst[500000],
// W[64*256] f32, b[64] f32. Output: f32[500000*64].
// ---------------------------------------------------------------------------
extern "C" void kernel_launch(void* const* d_in, const int* in_sizes, int n_in,
                              void* d_out, int out_size) {
    const float* h   = (const float*)d_in[0];
    const void*  src = d_in[1];
    const void*  dst = d_in[2];
    const float* W   = (const float*)d_in[3];
    const float* b   = (const float*)d_in[4];
    float* out = (float*)d_out;
    (void)in_sizes; (void)n_in; (void)out_size;

    cudaFuncSetAttribute(node_gemm_f16,
                         cudaFuncAttributeMaxDynamicSharedMemorySize, GEMM_SMEM);

    const int gemm_blocks = (N_NODES + GM - 1) / GM;   // 391
    node_gemm_f16<<<gemm_blocks, GTHREADS, GEMM_SMEM>>>(h, W, b);

    // 64 edges per block (8 warps x 8): ceil(500000/64) = 7813
    edge_scatter_kernel<<<(N_EDGES + 63) / 64, 256>>>(src, dst, out);
}